// round 14
// baseline (speedup 1.0000x reference)
#include <cuda_runtime.h>
#include <math.h>

#define NPTS   2048
#define NGRID  32768   // 32^3
#define NB     8
#define CD     8       // cells per axis
#define NCELL  512     // 8^3
#define CAP    320     // staged-candidate capacity (mean 108, +21 sigma)
#define TWO_PI_F 6.283185307179586f
#define HCELL   (TWO_PI_F / 8.0f)
#define INV_HCELL (8.0f / TWO_PI_F)
#define EPSB    0.0009765625f     // 2^-10 positivity bias for packed keys
#define KEYMASK 0xFFFFF000u       // sign+exp+11 mantissa bits; low 12 = payload
#define FLAGBIT 0x800u            // payload bit 11: sorted-global index entry
#define SENT    0x7F000000u       // huge finite sentinel key

// Scratch (device globals; no allocations allowed)
__device__ float4 d_pts[2][NPTS];           // sorted-by-cell: (-2x,-2y,-2z, |c|^2)
__device__ int    d_gidx[2][NPTS];          // sorted pos -> original point index
__device__ int    d_cellStart[2][NCELL + 1];
__device__ int    d_cnt[2][NCELL];          // zero at load; re-zeroed by div_kernel
__device__ int    d_ofs[2][NCELL];          // rewritten by scan_kernel each run
__device__ float  g_flows[2 * NGRID * 3];   // interpolated grid flows

// lattice index i belongs to cell floor(8i/31); first index of cell c = ceil(31c/8).
// For CD=8 every cell has EXACTLY 4 lattice indices per axis -> nq = 64 per cell.
__device__ __forceinline__ int axis_start(int c) { return (31 * c + 7) >> 3; }

__device__ __forceinline__ int cell_of(float x, float y, float z)
{
    int cx = min(CD - 1, max(0, (int)(x * INV_HCELL)));
    int cy = min(CD - 1, max(0, (int)(y * INV_HCELL)));
    int cz = min(CD - 1, max(0, (int)(z * INV_HCELL)));
    return (cx << 6) | (cy << 3) | cz;
}

// Branchless insert of `key` into the 8-element working set bd[].
// Bubble pass: the ejected value is provably max(key, bd[0..7]) for ANY
// element order, so the 8-smallest SET is maintained even on unsorted bd.
__device__ __forceinline__ void ins8(unsigned* bd, unsigned key)
{
#pragma unroll
    for (int k = 0; k < NB; ++k) {
        unsigned lo = min(bd[k], key);
        key = max(bd[k], key);
        bd[k] = lo;
    }
}

// ---------------------------------------------------------------------------
// Kernel 1a: count points per cell (global atomics, wide grid for MLP).
// ---------------------------------------------------------------------------
__global__ __launch_bounds__(256)
void count_kernel(const float* __restrict__ coords, float* __restrict__ out)
{
    int gid = blockIdx.x * 256 + threadIdx.x;    // 0 .. 4095
    int b = gid >> 11;
    int j = gid & (NPTS - 1);
    const float* c = coords + (b * NPTS + j) * 3;
    atomicAdd(&d_cnt[b][cell_of(c[0], c[1], c[2])], 1);
    if (gid == 0) out[0] = 0.0f;
}

// ---------------------------------------------------------------------------
// Kernel 1b: exclusive prefix scan over 512 cells per batch (1 warp/batch).
// ---------------------------------------------------------------------------
__global__ __launch_bounds__(32)
void scan_kernel()
{
    const int b = blockIdx.x;
    const int lane = threadIdx.x;
    const int base = lane * 16;
    int v[16];
    int lanesum = 0;
#pragma unroll
    for (int k = 0; k < 16; ++k) {
        v[k] = d_cnt[b][base + k];
        lanesum += v[k];
    }
    int ex = lanesum;
#pragma unroll
    for (int off = 1; off < 32; off <<= 1) {
        int n = __shfl_up_sync(0xFFFFFFFFu, ex, off);
        if (lane >= off) ex += n;
    }
    ex -= lanesum;
    int run = ex;
#pragma unroll
    for (int k = 0; k < 16; ++k) {
        d_cellStart[b][base + k] = run;
        d_ofs[b][base + k] = run;
        run += v[k];
    }
    if (lane == 31) d_cellStart[b][NCELL] = run;    // = NPTS
}

// ---------------------------------------------------------------------------
// Kernel 1c: scatter points into cell-sorted order (coords L2-hot now).
// ---------------------------------------------------------------------------
__global__ __launch_bounds__(256)
void scatter_kernel(const float* __restrict__ coords)
{
    int gid = blockIdx.x * 256 + threadIdx.x;    // 0 .. 4095
    int b = gid >> 11;
    int j = gid & (NPTS - 1);
    const float* c = coords + (b * NPTS + j) * 3;
    float x = c[0], y = c[1], z = c[2];
    int pos = atomicAdd(&d_ofs[b][cell_of(x, y, z)], 1);
    d_pts[b][pos]  = make_float4(-2.0f * x, -2.0f * y, -2.0f * z,
                                 x * x + y * y + z * z);
    d_gidx[b][pos] = j;
}

// ---------------------------------------------------------------------------
// Kernel 2: exact 8-NN + IDW. One 128-thread block (4 warps) per (batch,
// cell). Warps (2c, 2c+1) both own chunk c's 32 queries; each scans HALF
// the staged candidates (dual chains), the partner publishes its 8-key set
// via smem, the primary folds it in and alone runs coverage/expansion/IDW.
// Doubles resident warps and halves per-warp serial scan (latency-bound
// fix). Box coverage proof + bound-skipped box-growth expansion
// (exact-global fallback on overflow) keeps the top-8 exact for any input.
// ---------------------------------------------------------------------------
__global__ __launch_bounds__(128, 8)
void knn_cell_kernel(const float* __restrict__ flow,
                     const float* __restrict__ grid_coords)
{
    __shared__ float4   pts_s[CAP];
    __shared__ int      sidx_s[CAP];
    __shared__ int      meta_s[2];       // [0]=sN, [1]=overflow flag
    __shared__ unsigned mg_s[2][32][NB]; // partner top-8 sets per chunk/lane

    const int b    = blockIdx.x >> 9;       // /512
    const int cell = blockIdx.x & (NCELL - 1);
    const int cx = cell >> 6;
    const int cy = (cell >> 3) & 7;
    const int cz = cell & 7;

    const int bx0 = max(cx - 1, 0), bx1 = min(cx + 1, CD - 1);
    const int by0 = max(cy - 1, 0), by1 = min(cy + 1, CD - 1);
    const int bz0 = max(cz - 1, 0), bz1 = min(cz + 1, CD - 1);
    const int ey = by1 - by0 + 1, ez = bz1 - bz0 + 1;
    const int ncells = (bx1 - bx0 + 1) * ey * ez;   // 8..27

    const int tid  = threadIdx.x;
    const int wid  = tid >> 5, lane = tid & 31;

    // --- staging: warp 0, one lane per candidate cell, shfl prefix scan ---
    if (tid < 32) {
        int n = 0, s0 = 0;
        if (lane < ncells) {
            int jx = bx0 + lane / (ey * ez);
            int rem = lane % (ey * ez);
            int jy = by0 + rem / ez;
            int jz = bz0 + rem % ez;
            int cid = (jx << 6) | (jy << 3) | jz;
            s0 = d_cellStart[b][cid];
            n  = d_cellStart[b][cid + 1] - s0;
        }
        int pre = n;
#pragma unroll
        for (int off = 1; off < 32; off <<= 1) {
            int t = __shfl_up_sync(0xFFFFFFFFu, pre, off);
            if (lane >= off) pre += t;
        }
        int total = __shfl_sync(0xFFFFFFFFu, pre, 31);
        pre -= n;                       // exclusive prefix
        if (lane == 0) { meta_s[0] = total; meta_s[1] = (total > CAP); }
        if (total <= CAP && lane < ncells) {
            for (int i = 0; i < n; ++i) {
                pts_s[pre + i]  = d_pts[b][s0 + i];
                sidx_s[pre + i] = s0 + i;
            }
        }
    }
    __syncthreads();
    const int  sN       = meta_s[0];
    const bool overflow = (meta_s[1] != 0);

    // --- query assignment: warps (2c, 2c+1) share chunk c's 32 queries ---
    const int chunk = wid >> 1;         // 0 or 1
    const int sub   = wid & 1;          // 0 = primary, 1 = partner
    const int ql = chunk * 32 + lane;   // 0..63
    const int lz = ql & 3, ly = (ql >> 2) & 3, lx = ql >> 4;
    const int ix = axis_start(cx) + lx;
    const int iy = axis_start(cy) + ly;
    const int iz = axis_start(cz) + lz;
    const int m = ((ix << 5) + iy) * 32 + iz;     // meshgrid 'ij' flattening

    const float* g = grid_coords + ((size_t)b * NGRID + (size_t)m) * 3;
    const float gx = g[0], gy = g[1], gz = g[2];
    const float g2 = gx * gx + gy * gy + gz * gz;
    const float G  = g2 + EPSB;         // keyed d2 = |g-c|^2 + EPSB > 0 always

    unsigned bd[NB];

    if (!overflow) {
        // split candidates: primary [0,h), partner [h,sN)
        const int h  = (sN >> 1) & ~1;
        const int jb = sub ? h : 0;
        const int je = sub ? sN : h;
        unsigned bdA[NB], bdB[NB];
#pragma unroll
        for (int k = 0; k < NB; ++k) { bdA[k] = SENT; bdB[k] = SENT; }
        int j = jb;
        for (; j + 1 < je; j += 2) {    // dual chains: 2x chain ILP
            float4 p0 = pts_s[j];
            float4 p1 = pts_s[j + 1];
            float d0 = fmaf(gx, p0.x, fmaf(gy, p0.y, fmaf(gz, p0.z, p0.w))) + G;
            float d1 = fmaf(gx, p1.x, fmaf(gy, p1.y, fmaf(gz, p1.z, p1.w))) + G;
            ins8(bdA, (__float_as_uint(d0) & KEYMASK) | (unsigned)j);
            ins8(bdB, (__float_as_uint(d1) & KEYMASK) | (unsigned)(j + 1));
        }
        if (j < je) {
            float4 p0 = pts_s[j];
            float d0 = fmaf(gx, p0.x, fmaf(gy, p0.y, fmaf(gz, p0.z, p0.w))) + G;
            ins8(bdA, (__float_as_uint(d0) & KEYMASK) | (unsigned)j);
        }
        // sorted-merge of the two ascending chains -> SET of 8 smallest
#pragma unroll
        for (int k = 0; k < NB; ++k) bd[k] = min(bdA[k], bdB[NB - 1 - k]);
    } else {
        // cold fallback (primary warps only): full ring-1 box from global
#pragma unroll
        for (int k = 0; k < NB; ++k) bd[k] = SENT;
        if (sub == 0) {
            for (int jx = bx0; jx <= bx1; ++jx)
                for (int jy = by0; jy <= by1; ++jy) {
                    int c0 = (jx << 6) | (jy << 3) | bz0;
                    int s0 = d_cellStart[b][c0];
                    int s1 = d_cellStart[b][c0 + (bz1 - bz0) + 1];
                    for (int s = s0; s < s1; ++s) {
                        float4 p = d_pts[b][s];
                        float d2 = fmaf(gx, p.x, fmaf(gy, p.y, fmaf(gz, p.z, p.w))) + G;
                        ins8(bd, (__float_as_uint(d2) & KEYMASK) | FLAGBIT | (unsigned)s);
                    }
                }
        }
    }

    // partner publishes its set; primary folds it in
    if (sub == 1) {
#pragma unroll
        for (int k = 0; k < NB; ++k) mg_s[chunk][lane][k] = bd[k];
    }
    __syncthreads();
    if (sub == 1) return;               // partner warps done
#pragma unroll
    for (int k = 0; k < NB; ++k) ins8(bd, mg_s[chunk][lane][k]);

    // --- box coverage proof + bound-skipped box-growth expansion ---
    bool haveBox = false;
    float bxl, bxh, byl, byh, bzl, bzh;
    int ox0 = bx0, ox1 = bx1, oy0 = by0, oy1 = by1, oz0 = bz0, oz1 = bz1;
    while (true) {
        float cov = 1e30f;
        if (ox0 > 0)      cov = fminf(cov, gx - (float)ox0 * HCELL);
        if (ox1 < CD - 1) cov = fminf(cov, (float)(ox1 + 1) * HCELL - gx);
        if (oy0 > 0)      cov = fminf(cov, gy - (float)oy0 * HCELL);
        if (oy1 < CD - 1) cov = fminf(cov, (float)(oy1 + 1) * HCELL - gy);
        if (oz0 > 0)      cov = fminf(cov, gz - (float)oz0 * HCELL);
        if (oz1 < CD - 1) cov = fminf(cov, (float)(oz1 + 1) * HCELL - gz);
        unsigned mx = bd[0];
#pragma unroll
        for (int k = 1; k < NB; ++k) mx = max(mx, bd[k]);
        float d2_8 = __uint_as_float(mx & KEYMASK);
        bool full = (ox0 == 0 && ox1 == CD - 1 && oy0 == 0 && oy1 == CD - 1 &&
                     oz0 == 0 && oz1 == CD - 1);
        bool ok = full || (d2_8 * 1.001f + 0.01f <= cov * cov);
        if (__all_sync(0xFFFFFFFFu, ok)) break;

        if (!haveBox) {       // lazy warp query-bbox (expansion path only)
            bxl = bxh = gx; byl = byh = gy; bzl = bzh = gz;
#pragma unroll
            for (int off = 16; off > 0; off >>= 1) {
                bxl = fminf(bxl, __shfl_xor_sync(0xFFFFFFFFu, bxl, off));
                bxh = fmaxf(bxh, __shfl_xor_sync(0xFFFFFFFFu, bxh, off));
                byl = fminf(byl, __shfl_xor_sync(0xFFFFFFFFu, byl, off));
                byh = fmaxf(byh, __shfl_xor_sync(0xFFFFFFFFu, byh, off));
                bzl = fminf(bzl, __shfl_xor_sync(0xFFFFFFFFu, bzl, off));
                bzh = fmaxf(bzh, __shfl_xor_sync(0xFFFFFFFFu, bzh, off));
            }
            haveBox = true;
        }

        // warp-max current 8th (threshold for safe cell skipping this round)
        unsigned wmk = __reduce_max_sync(0xFFFFFFFFu, mx);
        float wmax = __uint_as_float(wmk & KEYMASK);

        // grow box by 1 in every non-domain direction; scan new (unskipped) cells
        int nx0 = max(ox0 - 1, 0), nx1 = min(ox1 + 1, CD - 1);
        int ny0 = max(oy0 - 1, 0), ny1 = min(oy1 + 1, CD - 1);
        int nz0 = max(oz0 - 1, 0), nz1 = min(oz1 + 1, CD - 1);
        for (int jx = nx0; jx <= nx1; ++jx)
            for (int jy = ny0; jy <= ny1; ++jy)
                for (int jz = nz0; jz <= nz1; ++jz) {
                    bool inOld = (jx >= ox0 && jx <= ox1 &&
                                  jy >= oy0 && jy <= oy1 &&
                                  jz >= oz0 && jz <= oz1);
                    if (inOld) continue;
                    float clx = (float)jx * HCELL;
                    float cly = (float)jy * HCELL;
                    float clz = (float)jz * HCELL;
                    float gxd = fmaxf(0.0f, fmaxf(clx - bxh, bxl - (clx + HCELL)));
                    float gyd = fmaxf(0.0f, fmaxf(cly - byh, byl - (cly + HCELL)));
                    float gzd = fmaxf(0.0f, fmaxf(clz - bzh, bzl - (clz + HCELL)));
                    float d2min = gxd * gxd + gyd * gyd + gzd * gzd;
                    if (d2min * 0.999f - 0.01f > wmax) continue;   // provably safe
                    int cid = (jx << 6) | (jy << 3) | jz;
                    int s0 = d_cellStart[b][cid];
                    int s1 = d_cellStart[b][cid + 1];
                    for (int s = s0; s < s1; ++s) {
                        float4 p = d_pts[b][s];
                        float d2 = fmaf(gx, p.x, fmaf(gy, p.y, fmaf(gz, p.z, p.w))) + G;
                        ins8(bd, (__float_as_uint(d2) & KEYMASK) |
                                  FLAGBIT | (unsigned)s);
                    }
                }
        ox0 = nx0; ox1 = nx1; oy0 = ny0; oy1 = ny1; oz0 = nz0; oz1 = nz1;
    }

    // --- IDW on exact recomputed distances (bd order irrelevant) ---
    {
        const float* fb = flow + b * NPTS * 3;
        float wsum = 0.f, fxa = 0.f, fya = 0.f, fza = 0.f;
#pragma unroll
        for (int k = 0; k < NB; ++k) {
            unsigned e = bd[k] & 0xFFFu;
            int s = (e & FLAGBIT) ? (int)(e & 0x7FFu) : sidx_s[e];
            float4 p = d_pts[b][s];
            float d2f = fmaf(gx, p.x, fmaf(gy, p.y, fmaf(gz, p.z, p.w))) + g2;
            d2f = fmaxf(d2f, 0.0f);
            float rsq = __frsqrt_rn(fmaxf(d2f, 1e-30f));
            float dist = d2f * rsq;                 // sqrt(d2f)
            float tt = dist + 1e-8f;
            float w = __fdividef(1.0f, tt * tt);
            wsum += w;
            int gi = d_gidx[b][s];
            fxa = fmaf(w, fb[3 * gi + 0], fxa);
            fya = fmaf(w, fb[3 * gi + 1], fya);
            fza = fmaf(w, fb[3 * gi + 2], fza);
        }
        float inv = __fdividef(1.0f, wsum);
        float* o = g_flows + ((size_t)b * NGRID + (size_t)m) * 3;
        o[0] = fxa * inv;
        o[1] = fya * inv;
        o[2] = fza * inv;
    }
}

// ---------------------------------------------------------------------------
// Kernel 3: divergence (torch.gradient semantics, h = 2pi/32) + mean(|div|).
// Blocks 0-3 also re-zero d_cnt for the next graph replay.
// ---------------------------------------------------------------------------
__device__ __forceinline__ float gf_at(const float* base, int x, int y, int z, int c)
{
    return base[((((x << 5) + y) << 5) + z) * 3 + c];
}

__global__ __launch_bounds__(256)
void div_kernel(float* __restrict__ out)
{
    const float H     = TWO_PI_F / 32.0f;
    const float invH  = 1.0f / H;
    const float inv2H = 0.5f / H;

    if (blockIdx.x < 4)
        ((int*)d_cnt)[blockIdx.x * 256 + threadIdx.x] = 0;   // 1024 ints total

    int t = blockIdx.x * 256 + threadIdx.x;   // 0 .. 65535
    int b = t >> 15;
    int m = t & (NGRID - 1);
    int iz = m & 31;
    int iy = (m >> 5) & 31;
    int ix = m >> 10;

    const float* base = g_flows + (size_t)b * NGRID * 3;

    float dx, dy, dz;
    if (ix == 0)       dx = (gf_at(base, 1, iy, iz, 0)      - gf_at(base, 0, iy, iz, 0))      * invH;
    else if (ix == 31) dx = (gf_at(base, 31, iy, iz, 0)     - gf_at(base, 30, iy, iz, 0))     * invH;
    else               dx = (gf_at(base, ix + 1, iy, iz, 0) - gf_at(base, ix - 1, iy, iz, 0)) * inv2H;

    if (iy == 0)       dy = (gf_at(base, ix, 1, iz, 1)      - gf_at(base, ix, 0, iz, 1))      * invH;
    else if (iy == 31) dy = (gf_at(base, ix, 31, iz, 1)     - gf_at(base, ix, 30, iz, 1))     * invH;
    else               dy = (gf_at(base, ix, iy + 1, iz, 1) - gf_at(base, ix, iy - 1, iz, 1)) * inv2H;

    if (iz == 0)       dz = (gf_at(base, ix, iy, 1, 2)      - gf_at(base, ix, iy, 0, 2))      * invH;
    else if (iz == 31) dz = (gf_at(base, ix, iy, 31, 2)     - gf_at(base, ix, iy, 30, 2))     * invH;
    else               dz = (gf_at(base, ix, iy, iz + 1, 2) - gf_at(base, ix, iy, iz - 1, 2)) * inv2H;

    float v = fabsf(dx + dy + dz);

    __shared__ float sdata[256];
    sdata[threadIdx.x] = v;
    __syncthreads();
#pragma unroll
    for (int s = 128; s >= 32; s >>= 1) {
        if (threadIdx.x < s) sdata[threadIdx.x] += sdata[threadIdx.x + s];
        __syncthreads();
    }
    if (threadIdx.x < 32) {
        float r = sdata[threadIdx.x];
#pragma unroll
        for (int off = 16; off > 0; off >>= 1)
            r += __shfl_down_sync(0xFFFFFFFFu, r, off);
        if (threadIdx.x == 0)
            atomicAdd(out, r * (1.0f / 65536.0f));
    }
}

// ---------------------------------------------------------------------------
// Launch. Sequence {count, scan, scatter, knn, div}: knn at sequence
// index 3 = the confirmed ncu capture slot.
// ---------------------------------------------------------------------------
extern "C" void kernel_launch(void* const* d_in, const int* in_sizes, int n_in,
                              void* d_out, int out_size)
{
    const float* flow        = (const float*)d_in[0];   // (2, 2048, 3)
    const float* coords      = (const float*)d_in[1];   // (2, 2048, 3)
    const float* grid_coords = (const float*)d_in[2];   // (2, 32768, 3)
    float* out = (float*)d_out;                         // scalar

    count_kernel<<<16, 256>>>(coords, out);
    scan_kernel<<<2, 32>>>();
    scatter_kernel<<<16, 256>>>(coords);
    knn_cell_kernel<<<2 * NCELL, 128>>>(flow, grid_coords);
    div_kernel<<<256, 256>>>(out);
}

// round 15
// speedup vs baseline: 1.0078x; 1.0078x over previous
#include <cuda_runtime.h>
#include <math.h>

#define NPTS   2048
#define NGRID  32768   // 32^3
#define NB     8
#define CD     8       // cells per axis
#define NCELL  512     // 8^3
#define CAP    320     // staged-candidate capacity (mean 108, +21 sigma)
#define TWO_PI_F 6.283185307179586f
#define HCELL   (TWO_PI_F / 8.0f)
#define INV_HCELL (8.0f / TWO_PI_F)
#define EPSB    0.0009765625f     // 2^-10 positivity bias for packed keys
#define KEYMASK 0xFFFFF000u       // sign+exp+11 mantissa bits; low 12 = payload
#define FLAGBIT 0x800u            // payload bit 11: sorted-global index entry
#define SENT    0x7F000000u       // huge finite sentinel key

// Scratch (device globals; no allocations allowed)
__device__ float4 d_pts[2][NPTS];           // sorted-by-cell: (-2x,-2y,-2z, |c|^2)
__device__ int    d_gidx[2][NPTS];          // sorted pos -> original point index
__device__ int    d_cellStart[2][NCELL + 1];
__device__ int    d_cnt[2][NCELL];          // zero at load; re-zeroed by div_kernel
__device__ int    d_ofs[2][NCELL];          // rewritten by scan_kernel each run
__device__ float  g_flows[2 * NGRID * 3];   // interpolated grid flows

// lattice index i belongs to cell floor(8i/31); first index of cell c = ceil(31c/8).
// For CD=8 every cell has EXACTLY 4 lattice indices per axis -> nq = 64 per cell.
__device__ __forceinline__ int axis_start(int c) { return (31 * c + 7) >> 3; }

__device__ __forceinline__ int cell_of(float x, float y, float z)
{
    int cx = min(CD - 1, max(0, (int)(x * INV_HCELL)));
    int cy = min(CD - 1, max(0, (int)(y * INV_HCELL)));
    int cz = min(CD - 1, max(0, (int)(z * INV_HCELL)));
    return (cx << 6) | (cy << 3) | cz;
}

// Branchless insert of `key` into the 8-element working set bd[].
// Bubble pass: the ejected value is provably max(key, bd[0..7]) for ANY
// element order, so the 8-smallest SET is maintained even on unsorted bd.
__device__ __forceinline__ void ins8(unsigned* bd, unsigned key)
{
#pragma unroll
    for (int k = 0; k < NB; ++k) {
        unsigned lo = min(bd[k], key);
        key = max(bd[k], key);
        bd[k] = lo;
    }
}

// ---------------------------------------------------------------------------
// Kernel 1a: count points per cell (global atomics, wide grid for MLP).
// ---------------------------------------------------------------------------
__global__ __launch_bounds__(256)
void count_kernel(const float* __restrict__ coords, float* __restrict__ out)
{
    int gid = blockIdx.x * 256 + threadIdx.x;    // 0 .. 4095
    int b = gid >> 11;
    int j = gid & (NPTS - 1);
    const float* c = coords + (b * NPTS + j) * 3;
    atomicAdd(&d_cnt[b][cell_of(c[0], c[1], c[2])], 1);
    if (gid == 0) out[0] = 0.0f;
}

// ---------------------------------------------------------------------------
// Kernel 1b: exclusive prefix scan over 512 cells per batch (1 warp/batch).
// ---------------------------------------------------------------------------
__global__ __launch_bounds__(32)
void scan_kernel()
{
    const int b = blockIdx.x;
    const int lane = threadIdx.x;
    const int base = lane * 16;
    int v[16];
    int lanesum = 0;
#pragma unroll
    for (int k = 0; k < 16; ++k) {
        v[k] = d_cnt[b][base + k];
        lanesum += v[k];
    }
    int ex = lanesum;
#pragma unroll
    for (int off = 1; off < 32; off <<= 1) {
        int n = __shfl_up_sync(0xFFFFFFFFu, ex, off);
        if (lane >= off) ex += n;
    }
    ex -= lanesum;
    int run = ex;
#pragma unroll
    for (int k = 0; k < 16; ++k) {
        d_cellStart[b][base + k] = run;
        d_ofs[b][base + k] = run;
        run += v[k];
    }
    if (lane == 31) d_cellStart[b][NCELL] = run;    // = NPTS
}

// ---------------------------------------------------------------------------
// Kernel 1c: scatter points into cell-sorted order (coords L2-hot now).
// ---------------------------------------------------------------------------
__global__ __launch_bounds__(256)
void scatter_kernel(const float* __restrict__ coords)
{
    int gid = blockIdx.x * 256 + threadIdx.x;    // 0 .. 4095
    int b = gid >> 11;
    int j = gid & (NPTS - 1);
    const float* c = coords + (b * NPTS + j) * 3;
    float x = c[0], y = c[1], z = c[2];
    int pos = atomicAdd(&d_ofs[b][cell_of(x, y, z)], 1);
    d_pts[b][pos]  = make_float4(-2.0f * x, -2.0f * y, -2.0f * z,
                                 x * x + y * y + z * z);
    d_gidx[b][pos] = j;
}

// ---------------------------------------------------------------------------
// Kernel 2: exact 8-NN + IDW. One 64-thread block (2 warps) per (batch,
// cell); each warp owns exactly one full 32-query chunk. Ring-1 staging is
// fully parallel: the box is <=9 CONTIGUOUS z-spans in cell-sorted d_pts;
// warp 0 fetches all span bounds in one L2 round-trip + 9-wide shfl scan,
// then ALL 64 threads copy spans cooperatively. Query coords are loaded
// BEFORE the staging barrier. Box coverage proof + bound-skipped box-growth
// expansion (exact-global fallback on overflow) keeps the top-8 exact.
// ---------------------------------------------------------------------------
__global__ __launch_bounds__(64, 8)
void knn_cell_kernel(const float* __restrict__ flow,
                     const float* __restrict__ grid_coords)
{
    __shared__ float4 pts_s[CAP];
    __shared__ int    sidx_s[CAP];
    __shared__ int    span_s0[9];      // global start of each span
    __shared__ int    span_bs[9];      // staged base offset of each span
    __shared__ int    span_n[9];       // span length
    __shared__ int    meta_s[2];       // [0]=sN, [1]=overflow flag

    const int b    = blockIdx.x >> 9;       // /512
    const int cell = blockIdx.x & (NCELL - 1);
    const int cx = cell >> 6;
    const int cy = (cell >> 3) & 7;
    const int cz = cell & 7;

    const int bx0 = max(cx - 1, 0), bx1 = min(cx + 1, CD - 1);
    const int by0 = max(cy - 1, 0), by1 = min(cy + 1, CD - 1);
    const int bz0 = max(cz - 1, 0), bz1 = min(cz + 1, CD - 1);
    const int ey = by1 - by0 + 1, ez = bz1 - bz0 + 1;
    const int nspan = (bx1 - bx0 + 1) * ey;         // 4..9 z-spans

    const int tid  = threadIdx.x;
    const int wid  = tid >> 5, lane = tid & 31;

    // --- query coords: load BEFORE the staging barrier (independent) ---
    const int ql = wid * 32 + lane;     // 0..63
    const int lz = ql & 3, ly = (ql >> 2) & 3, lx = ql >> 4;
    const int ix = axis_start(cx) + lx;
    const int iy = axis_start(cy) + ly;
    const int iz = axis_start(cz) + lz;
    const int m = ((ix << 5) + iy) * 32 + iz;     // meshgrid 'ij' flattening
    const float* g = grid_coords + ((size_t)b * NGRID + (size_t)m) * 3;
    const float gx = g[0], gy = g[1], gz = g[2];
    const float g2 = gx * gx + gy * gy + gz * gz;
    const float G  = g2 + EPSB;         // keyed d2 = |g-c|^2 + EPSB > 0 always

    // --- span bounds: warp 0, one lane per span, parallel L2 fetch ---
    if (tid < 32) {
        int n = 0, s0 = 0;
        if (lane < nspan) {
            int jx = bx0 + lane / ey;
            int jy = by0 + lane % ey;
            int c0 = (jx << 6) | (jy << 3) | bz0;
            s0 = d_cellStart[b][c0];
            n  = d_cellStart[b][c0 + ez] - s0;    // contiguous z-span
        }
        int pre = n;
#pragma unroll
        for (int off = 1; off < 32; off <<= 1) {
            int t = __shfl_up_sync(0xFFFFFFFFu, pre, off);
            if (lane >= off) pre += t;
        }
        int total = __shfl_sync(0xFFFFFFFFu, pre, 31);
        pre -= n;                       // exclusive prefix
        if (lane < nspan) {
            span_s0[lane] = s0;
            span_bs[lane] = pre;
            span_n[lane]  = n;
        }
        if (lane == 0) { meta_s[0] = total; meta_s[1] = (total > CAP); }
    }
    __syncthreads();
    const int  sN       = meta_s[0];
    const bool overflow = (meta_s[1] != 0);

    // --- cooperative span copy: ALL 64 threads, offsets from smem ---
    if (!overflow) {
        for (int r = 0; r < nspan; ++r) {
            int s0 = span_s0[r], bs = span_bs[r], n = span_n[r];
            for (int t = tid; t < n; t += 64) {
                pts_s[bs + t]  = d_pts[b][s0 + t];
                sidx_s[bs + t] = s0 + t;
            }
        }
    }
    __syncthreads();

    unsigned bd[NB];

    if (!overflow) {
        unsigned bdA[NB], bdB[NB];
#pragma unroll
        for (int k = 0; k < NB; ++k) { bdA[k] = SENT; bdB[k] = SENT; }
        int j = 0;
        for (; j + 1 < sN; j += 2) {    // dual chains: 2x chain ILP
            float4 p0 = pts_s[j];
            float4 p1 = pts_s[j + 1];
            float d0 = fmaf(gx, p0.x, fmaf(gy, p0.y, fmaf(gz, p0.z, p0.w))) + G;
            float d1 = fmaf(gx, p1.x, fmaf(gy, p1.y, fmaf(gz, p1.z, p1.w))) + G;
            ins8(bdA, (__float_as_uint(d0) & KEYMASK) | (unsigned)j);
            ins8(bdB, (__float_as_uint(d1) & KEYMASK) | (unsigned)(j + 1));
        }
        if (j < sN) {
            float4 p0 = pts_s[j];
            float d0 = fmaf(gx, p0.x, fmaf(gy, p0.y, fmaf(gz, p0.z, p0.w))) + G;
            ins8(bdA, (__float_as_uint(d0) & KEYMASK) | (unsigned)j);
        }
        // 8 smallest of two sorted-8 = elementwise min(A[i], B[7-i])
#pragma unroll
        for (int k = 0; k < NB; ++k) bd[k] = min(bdA[k], bdB[NB - 1 - k]);
    } else {
        // cold fallback: scan whole ring-1 box from global with exact keys
#pragma unroll
        for (int k = 0; k < NB; ++k) bd[k] = SENT;
        for (int jx = bx0; jx <= bx1; ++jx)
            for (int jy = by0; jy <= by1; ++jy) {
                int c0 = (jx << 6) | (jy << 3) | bz0;
                int s0 = d_cellStart[b][c0];
                int s1 = d_cellStart[b][c0 + ez];
                for (int s = s0; s < s1; ++s) {
                    float4 p = d_pts[b][s];
                    float d2 = fmaf(gx, p.x, fmaf(gy, p.y, fmaf(gz, p.z, p.w))) + G;
                    ins8(bd, (__float_as_uint(d2) & KEYMASK) | FLAGBIT | (unsigned)s);
                }
            }
    }

    // --- box coverage proof + bound-skipped box-growth expansion ---
    bool haveBox = false;
    float bxl, bxh, byl, byh, bzl, bzh;
    int ox0 = bx0, ox1 = bx1, oy0 = by0, oy1 = by1, oz0 = bz0, oz1 = bz1;
    while (true) {
        float cov = 1e30f;
        if (ox0 > 0)      cov = fminf(cov, gx - (float)ox0 * HCELL);
        if (ox1 < CD - 1) cov = fminf(cov, (float)(ox1 + 1) * HCELL - gx);
        if (oy0 > 0)      cov = fminf(cov, gy - (float)oy0 * HCELL);
        if (oy1 < CD - 1) cov = fminf(cov, (float)(oy1 + 1) * HCELL - gy);
        if (oz0 > 0)      cov = fminf(cov, gz - (float)oz0 * HCELL);
        if (oz1 < CD - 1) cov = fminf(cov, (float)(oz1 + 1) * HCELL - gz);
        unsigned mx = bd[0];
#pragma unroll
        for (int k = 1; k < NB; ++k) mx = max(mx, bd[k]);
        float d2_8 = __uint_as_float(mx & KEYMASK);
        bool full = (ox0 == 0 && ox1 == CD - 1 && oy0 == 0 && oy1 == CD - 1 &&
                     oz0 == 0 && oz1 == CD - 1);
        bool ok = full || (d2_8 * 1.001f + 0.01f <= cov * cov);
        if (__all_sync(0xFFFFFFFFu, ok)) break;

        if (!haveBox) {       // lazy warp query-bbox (expansion path only)
            bxl = bxh = gx; byl = byh = gy; bzl = bzh = gz;
#pragma unroll
            for (int off = 16; off > 0; off >>= 1) {
                bxl = fminf(bxl, __shfl_xor_sync(0xFFFFFFFFu, bxl, off));
                bxh = fmaxf(bxh, __shfl_xor_sync(0xFFFFFFFFu, bxh, off));
                byl = fminf(byl, __shfl_xor_sync(0xFFFFFFFFu, byl, off));
                byh = fmaxf(byh, __shfl_xor_sync(0xFFFFFFFFu, byh, off));
                bzl = fminf(bzl, __shfl_xor_sync(0xFFFFFFFFu, bzl, off));
                bzh = fmaxf(bzh, __shfl_xor_sync(0xFFFFFFFFu, bzh, off));
            }
            haveBox = true;
        }

        // warp-max current 8th (threshold for safe cell skipping this round)
        unsigned wmk = __reduce_max_sync(0xFFFFFFFFu, mx);
        float wmax = __uint_as_float(wmk & KEYMASK);

        // grow box by 1 in every non-domain direction; scan new (unskipped) cells
        int nx0 = max(ox0 - 1, 0), nx1 = min(ox1 + 1, CD - 1);
        int ny0 = max(oy0 - 1, 0), ny1 = min(oy1 + 1, CD - 1);
        int nz0 = max(oz0 - 1, 0), nz1 = min(oz1 + 1, CD - 1);
        for (int jx = nx0; jx <= nx1; ++jx)
            for (int jy = ny0; jy <= ny1; ++jy)
                for (int jz = nz0; jz <= nz1; ++jz) {
                    bool inOld = (jx >= ox0 && jx <= ox1 &&
                                  jy >= oy0 && jy <= oy1 &&
                                  jz >= oz0 && jz <= oz1);
                    if (inOld) continue;
                    float clx = (float)jx * HCELL;
                    float cly = (float)jy * HCELL;
                    float clz = (float)jz * HCELL;
                    float gxd = fmaxf(0.0f, fmaxf(clx - bxh, bxl - (clx + HCELL)));
                    float gyd = fmaxf(0.0f, fmaxf(cly - byh, byl - (cly + HCELL)));
                    float gzd = fmaxf(0.0f, fmaxf(clz - bzh, bzl - (clz + HCELL)));
                    float d2min = gxd * gxd + gyd * gyd + gzd * gzd;
                    if (d2min * 0.999f - 0.01f > wmax) continue;   // provably safe
                    int cid = (jx << 6) | (jy << 3) | jz;
                    int s0 = d_cellStart[b][cid];
                    int s1 = d_cellStart[b][cid + 1];
                    for (int s = s0; s < s1; ++s) {
                        float4 p = d_pts[b][s];
                        float d2 = fmaf(gx, p.x, fmaf(gy, p.y, fmaf(gz, p.z, p.w))) + G;
                        ins8(bd, (__float_as_uint(d2) & KEYMASK) |
                                  FLAGBIT | (unsigned)s);
                    }
                }
        ox0 = nx0; ox1 = nx1; oy0 = ny0; oy1 = ny1; oz0 = nz0; oz1 = nz1;
    }

    // --- IDW on exact recomputed distances (bd order irrelevant) ---
    {
        const float* fb = flow + b * NPTS * 3;
        float wsum = 0.f, fxa = 0.f, fya = 0.f, fza = 0.f;
#pragma unroll
        for (int k = 0; k < NB; ++k) {
            unsigned e = bd[k] & 0xFFFu;
            int s = (e & FLAGBIT) ? (int)(e & 0x7FFu) : sidx_s[e];
            float4 p = d_pts[b][s];
            float d2f = fmaf(gx, p.x, fmaf(gy, p.y, fmaf(gz, p.z, p.w))) + g2;
            d2f = fmaxf(d2f, 0.0f);
            float rsq = __frsqrt_rn(fmaxf(d2f, 1e-30f));
            float dist = d2f * rsq;                 // sqrt(d2f)
            float tt = dist + 1e-8f;
            float w = __fdividef(1.0f, tt * tt);
            wsum += w;
            int gi = d_gidx[b][s];
            fxa = fmaf(w, fb[3 * gi + 0], fxa);
            fya = fmaf(w, fb[3 * gi + 1], fya);
            fza = fmaf(w, fb[3 * gi + 2], fza);
        }
        float inv = __fdividef(1.0f, wsum);
        float* o = g_flows + ((size_t)b * NGRID + (size_t)m) * 3;
        o[0] = fxa * inv;
        o[1] = fya * inv;
        o[2] = fza * inv;
    }
}

// ---------------------------------------------------------------------------
// Kernel 3: divergence (torch.gradient semantics, h = 2pi/32) + mean(|div|).
// Blocks 0-3 also re-zero d_cnt for the next graph replay.
// ---------------------------------------------------------------------------
__device__ __forceinline__ float gf_at(const float* base, int x, int y, int z, int c)
{
    return base[((((x << 5) + y) << 5) + z) * 3 + c];
}

__global__ __launch_bounds__(256)
void div_kernel(float* __restrict__ out)
{
    const float H     = TWO_PI_F / 32.0f;
    const float invH  = 1.0f / H;
    const float inv2H = 0.5f / H;

    if (blockIdx.x < 4)
        ((int*)d_cnt)[blockIdx.x * 256 + threadIdx.x] = 0;   // 1024 ints total

    int t = blockIdx.x * 256 + threadIdx.x;   // 0 .. 65535
    int b = t >> 15;
    int m = t & (NGRID - 1);
    int iz = m & 31;
    int iy = (m >> 5) & 31;
    int ix = m >> 10;

    const float* base = g_flows + (size_t)b * NGRID * 3;

    float dx, dy, dz;
    if (ix == 0)       dx = (gf_at(base, 1, iy, iz, 0)      - gf_at(base, 0, iy, iz, 0))      * invH;
    else if (ix == 31) dx = (gf_at(base, 31, iy, iz, 0)     - gf_at(base, 30, iy, iz, 0))     * invH;
    else               dx = (gf_at(base, ix + 1, iy, iz, 0) - gf_at(base, ix - 1, iy, iz, 0)) * inv2H;

    if (iy == 0)       dy = (gf_at(base, ix, 1, iz, 1)      - gf_at(base, ix, 0, iz, 1))      * invH;
    else if (iy == 31) dy = (gf_at(base, ix, 31, iz, 1)     - gf_at(base, ix, 30, iz, 1))     * invH;
    else               dy = (gf_at(base, ix, iy + 1, iz, 1) - gf_at(base, ix, iy - 1, iz, 1)) * inv2H;

    if (iz == 0)       dz = (gf_at(base, ix, iy, 1, 2)      - gf_at(base, ix, iy, 0, 2))      * invH;
    else if (iz == 31) dz = (gf_at(base, ix, iy, 31, 2)     - gf_at(base, ix, iy, 30, 2))     * invH;
    else               dz = (gf_at(base, ix, iy, iz + 1, 2) - gf_at(base, ix, iy, iz - 1, 2)) * inv2H;

    float v = fabsf(dx + dy + dz);

    __shared__ float sdata[256];
    sdata[threadIdx.x] = v;
    __syncthreads();
#pragma unroll
    for (int s = 128; s >= 32; s >>= 1) {
        if (threadIdx.x < s) sdata[threadIdx.x] += sdata[threadIdx.x + s];
        __syncthreads();
    }
    if (threadIdx.x < 32) {
        float r = sdata[threadIdx.x];
#pragma unroll
        for (int off = 16; off > 0; off >>= 1)
            r += __shfl_down_sync(0xFFFFFFFFu, r, off);
        if (threadIdx.x == 0)
            atomicAdd(out, r * (1.0f / 65536.0f));
    }
}

// ---------------------------------------------------------------------------
// Launch. Sequence {count, scan, scatter, knn, div}: knn at sequence
// index 3 = the confirmed ncu capture slot.
// ---------------------------------------------------------------------------
extern "C" void kernel_launch(void* const* d_in, const int* in_sizes, int n_in,
                              void* d_out, int out_size)
{
    const float* flow        = (const float*)d_in[0];   // (2, 2048, 3)
    const float* coords      = (const float*)d_in[1];   // (2, 2048, 3)
    const float* grid_coords = (const float*)d_in[2];   // (2, 32768, 3)
    float* out = (float*)d_out;                         // scalar

    count_kernel<<<16, 256>>>(coords, out);
    scan_kernel<<<2, 32>>>();
    scatter_kernel<<<16, 256>>>(coords);
    knn_cell_kernel<<<2 * NCELL, 64>>>(flow, grid_coords);
    div_kernel<<<256, 256>>>(out);
}